// round 17
// baseline (speedup 1.0000x reference)
#include <cuda_runtime.h>
#include <cuda_fp16.h>
#include <stdint.h>

#define BATCH 4
#define TT    1024
#define DD    1024
#define HH    8
#define DKK   128
#define PP    2047
#define MHS   (BATCH*TT)
#define BK    32
#define ROWP  40                        // padded smem row stride (halves)
#define BUFA  (128*ROWP)                // 128-row buffer
#define BUFB  (64*ROWP)                 // 64-row buffer
#define STAGES 3
#define STG   (BUFA + BUFB)             // stage: A128 + B64
#define STGW  (2*BUFA)                  // stage: A128 + B128 (wide kernels)
#define DYN   (STAGES*STG*2)            // 46080 B
#define DYN4  (4*STG*2)                 // 61440 B
#define DYNW  (STAGES*STGW*2)           // 61440 B
#define PE_N  (PP*DD)
#define SCALE 0.08838834764831845f      // 1/sqrt(128)

// ---------------- scratch (device globals; all one-term fp16) ----------------
__device__ __half g_hsh[MHS*DD];
__device__ __half g_peh[PE_N];
__device__ __half g_Wqh[DD*DD], g_Wkh[DD*DD], g_Wvh[DD*DD];
__device__ __half g_Woh[DD*DD], g_Wph[DD*DD];
__device__ __half g_quh[BATCH*HH*TT*DKK];
__device__ __half g_qvh[BATCH*HH*TT*DKK];
__device__ __half g_kh [BATCH*HH*TT*DKK];
__device__ __half g_vTh[BATCH*HH*DKK*TT];           // (b,h,d,t)
__device__ __half g_ph [HH*PP*DKK];
__device__ __half g_ath[(size_t)BATCH*HH*TT*TT];    // probs
__device__ __half g_oh [MHS*DD];
__device__ __half g_scores[(size_t)BATCH*HH*TT*TT]; // 67 MB fp16, pre-scaled

typedef const __half* hp;

// ---------------- helpers ---------------------------------------------------
__device__ __forceinline__ uint32_t cvta_s(const void* p)
{
    uint32_t a;
    asm("{ .reg .u64 t; cvta.to.shared.u64 t, %1; cvt.u32.u64 %0, t; }" : "=r"(a) : "l"(p));
    return a;
}

#define MMA_F16(D, A, B0, B1)                                              \
    asm volatile("mma.sync.aligned.m16n8k16.row.col.f32.f16.f16.f32 "      \
                 "{%0,%1,%2,%3}, {%4,%5,%6,%7}, {%8,%9}, {%0,%1,%2,%3};"   \
                 : "+f"(D[0]), "+f"(D[1]), "+f"(D[2]), "+f"(D[3])          \
                 : "r"(A[0]), "r"(A[1]), "r"(A[2]), "r"(A[3]),             \
                   "r"(B0), "r"(B1))

#define LDSM4(R, addr)                                                          \
    asm volatile("ldmatrix.sync.aligned.m8n8.x4.shared.b16 {%0,%1,%2,%3}, [%4];"\
                 : "=r"((R)[0]), "=r"((R)[1]), "=r"((R)[2]), "=r"((R)[3])       \
                 : "r"(addr))

#define CP16(dst, src, okbytes)                                            \
    asm volatile("cp.async.cg.shared.global [%0], [%1], 16, %2;"           \
                 :: "r"(dst), "l"(src), "r"(okbytes) : "memory")
#define CP_COMMIT() asm volatile("cp.async.commit_group;" ::: "memory")
#define CP_WAIT(n)  asm volatile("cp.async.wait_group %0;" :: "n"(n) : "memory")

// ---------------- stage loaders ----------------------------------------------
__device__ __forceinline__ void load_stage(__half* sm, int s,
    hp Ah, int M, hp Bh, int N, int K, int row0, int col0, int k0)
{
    __half* st = sm + s * STG;
    const int tid = threadIdx.x;
    #pragma unroll
    for (int t = 0; t < 2; t++) {
        int slot = tid + t * 256;
        int r = slot >> 2, seg = slot & 3;
        int g = row0 + r;
        int ok = (g < M);
        const __half* sp = Ah + (size_t)(ok ? g : 0) * K + k0 + seg * 8;
        CP16(cvta_s(st + r * ROWP + seg * 8), sp, ok ? 16 : 0);
    }
    {
        int r = tid >> 2, seg = tid & 3;
        int g = col0 + r;
        int ok = (g < N);
        const __half* sp = Bh + (size_t)(ok ? g : 0) * K + k0 + seg * 8;
        CP16(cvta_s(st + BUFA + r * ROWP + seg * 8), sp, ok ? 16 : 0);
    }
}

// wide: B is 128 rows
__device__ __forceinline__ void load_stage_w(__half* sm, int s,
    hp Ah, int M, hp Bh, int N, int K, int row0, int col0, int k0)
{
    __half* st = sm + s * STGW;
    const int tid = threadIdx.x;
    #pragma unroll
    for (int t = 0; t < 2; t++) {
        int slot = tid + t * 256;
        int r = slot >> 2, seg = slot & 3;
        int g = row0 + r;
        int ok = (g < M);
        const __half* sp = Ah + (size_t)(ok ? g : 0) * K + k0 + seg * 8;
        CP16(cvta_s(st + r * ROWP + seg * 8), sp, ok ? 16 : 0);
    }
    #pragma unroll
    for (int t = 0; t < 2; t++) {
        int slot = tid + t * 256;
        int r = slot >> 2, seg = slot & 3;
        int g = col0 + r;
        int ok = (g < N);
        const __half* sp = Bh + (size_t)(ok ? g : 0) * K + k0 + seg * 8;
        CP16(cvta_s(st + BUFA + r * ROWP + seg * 8), sp, ok ? 16 : 0);
    }
}

// ---------------- BK=32 compute chunks ---------------------------------------
__device__ __forceinline__ void mma_chunk(const __half* st, int wm, int wn,
                                          int row_off, int col_off,
                                          float acc[2][4][4])
{
    #pragma unroll
    for (int kb = 0; kb < BK; kb += 16) {
        uint32_t a[2][4];
        #pragma unroll
        for (int i = 0; i < 2; i++) {
            int off = (wm * 32 + i * 16 + row_off) * ROWP + kb + col_off;
            LDSM4(a[i], cvta_s(st + off));
        }
        uint32_t b4[2][4];
        #pragma unroll
        for (int g = 0; g < 2; g++) {
            int off = (wn * 32 + g * 16 + row_off) * ROWP + kb + col_off;
            LDSM4(b4[g], cvta_s(st + BUFA + off));
        }
        #pragma unroll
        for (int g = 0; g < 2; g++) {
            MMA_F16(acc[0][g*2],   a[0], b4[g][0], b4[g][2]);
            MMA_F16(acc[1][g*2],   a[1], b4[g][0], b4[g][2]);
            MMA_F16(acc[0][g*2+1], a[0], b4[g][1], b4[g][3]);
            MMA_F16(acc[1][g*2+1], a[1], b4[g][1], b4[g][3]);
        }
    }
}

// wide: warp tile 32x64 (acc[2][8][4])
__device__ __forceinline__ void mma_chunk_w(const __half* st, int wm, int wn,
                                            int row_off, int col_off,
                                            float acc[2][8][4])
{
    #pragma unroll
    for (int kb = 0; kb < BK; kb += 16) {
        uint32_t a[2][4];
        #pragma unroll
        for (int i = 0; i < 2; i++) {
            int off = (wm * 32 + i * 16 + row_off) * ROWP + kb + col_off;
            LDSM4(a[i], cvta_s(st + off));
        }
        uint32_t b4[4][4];
        #pragma unroll
        for (int g = 0; g < 4; g++) {
            int off = (wn * 64 + g * 16 + row_off) * ROWP + kb + col_off;
            LDSM4(b4[g], cvta_s(st + BUFA + off));
        }
        #pragma unroll
        for (int g = 0; g < 4; g++) {
            MMA_F16(acc[0][g*2],   a[0], b4[g][0], b4[g][2]);
            MMA_F16(acc[1][g*2],   a[1], b4[g][0], b4[g][2]);
            MMA_F16(acc[0][g*2+1], a[0], b4[g][1], b4[g][3]);
            MMA_F16(acc[1][g*2+1], a[1], b4[g][1], b4[g][3]);
        }
    }
}

#define FRAG_DECLS                                         \
    const int lane = threadIdx.x & 31;                     \
    const int warp = threadIdx.x >> 5;                     \
    const int wm = warp >> 1, wn = warp & 1;               \
    const int mi = lane >> 3, lr8 = lane & 7;              \
    const int row_off = (mi & 1) * 8 + lr8;                \
    const int col_off = (mi >> 1) * 8;

// ---------------- generic K-streamed mainloop (proj) -------------------------
__device__ __forceinline__ void hmma_main(
    hp Ah, int M, hp Bh, int N,
    int K, int row0, int col0, float acc[2][4][4])
{
    extern __shared__ __half smv[];
    FRAG_DECLS

    const int niter = K >> 5;
    load_stage(smv, 0, Ah, M, Bh, N, K, row0, col0, 0);
    CP_COMMIT();
    if (niter > 1) load_stage(smv, 1, Ah, M, Bh, N, K, row0, col0, 32);
    CP_COMMIT();

    for (int it = 0; it < niter; it++) {
        if (it + 2 < niter) {
            load_stage(smv, (it + 2) % STAGES, Ah, M, Bh, N, K,
                       row0, col0, (it + 2) << 5);
            CP_COMMIT();
            CP_WAIT(2);
        } else if (it + 1 < niter) {
            CP_WAIT(1);
        } else {
            CP_WAIT(0);
        }
        __syncthreads();
        mma_chunk(smv + (it % STAGES) * STG, wm, wn, row_off, col_off, acc);
        __syncthreads();
    }
}

// ---------------- wide K-streamed mainloop (av, out) -------------------------
__device__ __forceinline__ void hmma_wide(
    hp Ah, int M, hp Bh, int N,
    int K, int row0, int col0, float acc[2][8][4])
{
    extern __shared__ __half smv[];
    FRAG_DECLS

    const int niter = K >> 5;
    load_stage_w(smv, 0, Ah, M, Bh, N, K, row0, col0, 0);
    CP_COMMIT();
    if (niter > 1) load_stage_w(smv, 1, Ah, M, Bh, N, K, row0, col0, 32);
    CP_COMMIT();

    for (int it = 0; it < niter; it++) {
        if (it + 2 < niter) {
            load_stage_w(smv, (it + 2) % STAGES, Ah, M, Bh, N, K,
                         row0, col0, (it + 2) << 5);
            CP_COMMIT();
            CP_WAIT(2);
        } else if (it + 1 < niter) {
            CP_WAIT(1);
        } else {
            CP_WAIT(0);
        }
        __syncthreads();
        mma_chunk_w(smv + (it % STAGES) * STGW, wm, wn, row_off, col_off, acc);
        __syncthreads();
    }
}

// ---------------- K=128 full-prefetch mainloop (ac, bd) ----------------------
__device__ __forceinline__ void hmma_k128(
    hp Ah, int M, hp Bh, int N, int row0, int col0, float acc[2][4][4])
{
    extern __shared__ __half smv[];
    FRAG_DECLS

    load_stage(smv, 0, Ah, M, Bh, N, DKK, row0, col0, 0);   CP_COMMIT();
    load_stage(smv, 1, Ah, M, Bh, N, DKK, row0, col0, 32);  CP_COMMIT();
    load_stage(smv, 2, Ah, M, Bh, N, DKK, row0, col0, 64);  CP_COMMIT();
    load_stage(smv, 3, Ah, M, Bh, N, DKK, row0, col0, 96);  CP_COMMIT();

    CP_WAIT(3); __syncthreads();
    mma_chunk(smv + 0 * STG, wm, wn, row_off, col_off, acc);
    CP_WAIT(2); __syncthreads();
    mma_chunk(smv + 1 * STG, wm, wn, row_off, col_off, acc);
    CP_WAIT(1); __syncthreads();
    mma_chunk(smv + 2 * STG, wm, wn, row_off, col_off, acc);
    CP_WAIT(0); __syncthreads();
    mma_chunk(smv + 3 * STG, wm, wn, row_off, col_off, acc);
}

// epilogue coordinate helpers
#define EPI_ROW(i, r)   (wm*32 + (i)*16 + grp + ((r) >> 1)*8)
#define EPI_COL(j, r)   (wn*32 + (j)*8 + qid*2 + ((r) & 1))
#define EPI_COLW(j, r)  (wn*64 + (j)*8 + qid*2 + ((r) & 1))
#define EPI_DECLS                                          \
    const int lane = threadIdx.x & 31;                     \
    const int warp = threadIdx.x >> 5;                     \
    const int grp = lane >> 2, qid = lane & 3;             \
    const int wm = warp >> 1, wn = warp & 1;

// ---------------- combined split (fp16 convert only, one launch) -------------
__global__ void k_split_all(const float* __restrict__ hs,
                            const float* __restrict__ pe,
                            const float* __restrict__ Wq,
                            const float* __restrict__ Wk,
                            const float* __restrict__ Wv,
                            const float* __restrict__ Wo,
                            const float* __restrict__ Wp)
{
    int i = blockIdx.x * blockDim.x + threadIdx.x;
    if (i < MHS*DD) { g_hsh[i] = __float2half_rn(hs[i]); return; }
    i -= MHS*DD;
    if (i < PE_N) { g_peh[i] = __float2half_rn(pe[i]); return; }
    i -= PE_N;
    if (i >= 5 * DD * DD) return;
    int w = i >> 20, o = i & (DD*DD - 1);
    const float* src = (w == 0) ? Wq : (w == 1) ? Wk : (w == 2) ? Wv
                     : (w == 3) ? Wo : Wp;
    __half* dst = (w == 0) ? g_Wqh : (w == 1) ? g_Wkh : (w == 2) ? g_Wvh
                : (w == 3) ? g_Woh : g_Wph;
    dst[o] = __float2half_rn(src[o]);
}

// ---------------- Q / K / P / V projections, single launch -------------------
__global__ void __launch_bounds__(256, 3)
k_proj(const float* __restrict__ bu, const float* __restrict__ bv)
{
    const int z = blockIdx.z;                     // 0:Q 1:K 2:P 3:V
    if (z == 2 && blockIdx.y >= 16) return;       // P has 16 row tiles
    hp Ah = (z == 2) ? g_peh : g_hsh;
    const int M = (z == 2) ? PP : MHS;
    hp Wh = (z == 0) ? g_Wqh : (z == 1) ? g_Wkh : (z == 2) ? g_Wph : g_Wvh;
    const int row0 = blockIdx.y * 128, col0 = blockIdx.x * 64;
    float acc[2][4][4] = {};
    hmma_main(Ah, M, Wh, DD, DD, row0, col0, acc);
    EPI_DECLS
    #pragma unroll
    for (int i = 0; i < 2; i++)
        #pragma unroll
        for (int j = 0; j < 4; j++)
            #pragma unroll
            for (int r = 0; r < 4; r++) {
                int m = row0 + EPI_ROW(i, r);
                int n = col0 + EPI_COL(j, r);
                int h = n >> 7, d = n & 127;
                float v = acc[i][j][r];
                if (z == 0) {
                    int b = m >> 10, t = m & 1023;
                    size_t idx = ((size_t)(b*HH + h)*TT + t)*DKK + d;
                    g_quh[idx] = __float2half_rn(v + bu[h*DKK + d]);
                    g_qvh[idx] = __float2half_rn(v + bv[h*DKK + d]);
                } else if (z == 1) {
                    int b = m >> 10, t = m & 1023;
                    size_t idx = ((size_t)(b*HH + h)*TT + t)*DKK + d;
                    g_kh[idx] = __float2half_rn(v);
                } else if (z == 2) {
                    if (m < PP) {
                        size_t idx = ((size_t)h*PP + m)*DKK + d;
                        g_ph[idx] = __float2half_rn(v);
                    }
                } else {
                    int b = m >> 10, t = m & 1023;
                    size_t it = ((size_t)(b*HH + h)*DKK + d)*TT + t;  // (b,h,d,t)
                    g_vTh[it] = __float2half_rn(v);
                }
            }
}

// ---------------- AC: scores = (qu @ k^T)·s per (b,h), fp16 out --------------
__global__ void __launch_bounds__(256, 3) k_ac()
{
    const int bh = blockIdx.z;
    const size_t ob = (size_t)bh * TT * DKK;
    const int row0 = blockIdx.y * 128, col0 = blockIdx.x * 64;
    float acc[2][4][4] = {};
    hmma_k128(g_quh + ob, TT, g_kh + ob, TT, row0, col0, acc);
    EPI_DECLS
    __half* C = g_scores + (size_t)bh * TT * TT;
    #pragma unroll
    for (int i = 0; i < 2; i++)
        #pragma unroll
        for (int j = 0; j < 4; j++)
            #pragma unroll
            for (int rr = 0; rr < 2; rr++) {
                int m = row0 + wm*32 + i*16 + grp + rr*8;
                int n = col0 + wn*32 + j*8 + qid*2;     // even -> 4B aligned
                __half2 h2 = __floats2half2_rn(acc[i][j][rr*2]   * SCALE,
                                               acc[i][j][rr*2+1] * SCALE);
                *reinterpret_cast<__half2*>(&C[(size_t)m * TT + n]) = h2;
            }
}

// ---------------- BD: scores[m, n+m-1023] += (qv @ p^T)·s (rel-shift) --------
__global__ void __launch_bounds__(256, 3) k_bd()
{
    const int bh = blockIdx.z, h = bh & 7;
    const int my = blockIdx.y;
    int cxmin = 896 - 128 * my;
    cxmin = (cxmin > 0) ? (cxmin >> 6) : 0;
    const int cx = blockIdx.x + cxmin;
    const int row0 = my * 128, col0 = cx * 64;
    const size_t oa = (size_t)bh * TT * DKK;
    const size_t op = (size_t)h * PP * DKK;
    float acc[2][4][4] = {};
    hmma_k128(g_qvh + oa, TT, g_ph + op, PP, row0, col0, acc);
    EPI_DECLS
    __half* C = g_scores + (size_t)bh * TT * TT;
    #pragma unroll
    for (int i = 0; i < 2; i++)
        #pragma unroll
        for (int j = 0; j < 4; j++)
            #pragma unroll
            for (int r = 0; r < 4; r++) {
                int m = row0 + EPI_ROW(i, r);
                int n = col0 + EPI_COL(j, r);
                if (n < PP) {
                    int k = n + m - 1023;
                    if ((unsigned)k < (unsigned)TT) {
                        size_t idx = (size_t)m * TT + k;
                        C[idx] = __float2half_rn(__half2float(C[idx])
                                                 + acc[i][j][r] * SCALE);
                    }
                }
            }
}

// ---------------- softmax: fp16 pre-scaled logits -> fp16 probs --------------
__global__ void k_softmax()
{
    const int row  = blockIdx.x * 8 + (threadIdx.x >> 5);
    const int lane = threadIdx.x & 31;
    const size_t rowoff = (size_t)row * TT;
    const uint4* r4 = reinterpret_cast<const uint4*>(g_scores + rowoff);

    float v[4][8];
    float m = -1e30f;
    #pragma unroll
    for (int i = 0; i < 4; i++) {
        uint4 pk = r4[i * 32 + lane];            // 8 halves
        const __half2* hh = reinterpret_cast<const __half2*>(&pk);
        #pragma unroll
        for (int q = 0; q < 4; q++) {
            float2 f = __half22float2(hh[q]);
            v[i][q*2]   = f.x;
            v[i][q*2+1] = f.y;
            m = fmaxf(m, fmaxf(f.x, f.y));
        }
    }
    #pragma unroll
    for (int o = 16; o > 0; o >>= 1) m = fmaxf(m, __shfl_xor_sync(~0u, m, o));

    float sum = 0.f;
    #pragma unroll
    for (int i = 0; i < 4; i++)
        #pragma unroll
        for (int e = 0; e < 8; e++) {
            v[i][e] = __expf(v[i][e] - m);
            sum += v[i][e];
        }
    #pragma unroll
    for (int o = 16; o > 0; o >>= 1) sum += __shfl_xor_sync(~0u, sum, o);

    float inv = __frcp_rn(sum);
    uint4* dst = reinterpret_cast<uint4*>(g_ath + rowoff);
    #pragma unroll
    for (int i = 0; i < 4; i++) {
        uint4 pk;
        __half2* hh = reinterpret_cast<__half2*>(&pk);
        #pragma unroll
        for (int q = 0; q < 4; q++)
            hh[q] = __floats2half2_rn(v[i][q*2] * inv, v[i][q*2+1] * inv);
        dst[i * 32 + lane] = pk;
    }
}

// ---------------- AV: o = attn @ v per (b,h)  (wide: full d in one tile) -----
__global__ void __launch_bounds__(256, 2) k_av()
{
    const int bh = blockIdx.y, b = bh >> 3, h = bh & 7;
    const size_t oa = (size_t)bh * TT * TT;
    const size_t ov = (size_t)bh * DKK * TT;
    const int row0 = blockIdx.x * 128;
    float acc[2][8][4] = {};
    hmma_wide(g_ath + oa, TT, g_vTh + ov, DKK, TT, row0, 0, acc);
    EPI_DECLS
    #pragma unroll
    for (int i = 0; i < 2; i++)
        #pragma unroll
        for (int j = 0; j < 8; j++)
            #pragma unroll
            for (int r = 0; r < 4; r++) {
                int m = row0 + EPI_ROW(i, r);
                int n = EPI_COLW(j, r);             // head-dim 0..127
                size_t idx = ((size_t)(b*TT + m)*HH + h)*DKK + n; // (b,t,h,d)
                g_oh[idx] = __float2half_rn(acc[i][j][r]);
            }
}

// ---------------- output projection (wide 128x128 tiles) ---------------------
__global__ void __launch_bounds__(256, 2) k_out(float* __restrict__ out)
{
    const int row0 = blockIdx.y * 128, col0 = blockIdx.x * 128;
    float acc[2][8][4] = {};
    hmma_wide(g_oh, MHS, g_Woh, DD, DD, row0, col0, acc);
    EPI_DECLS
    #pragma unroll
    for (int i = 0; i < 2; i++)
        #pragma unroll
        for (int j = 0; j < 8; j++)
            #pragma unroll
            for (int r = 0; r < 4; r++) {
                int m = row0 + EPI_ROW(i, r);
                int n = col0 + EPI_COLW(j, r);
                out[(size_t)m * DD + n] = acc[i][j][r];
            }
}

// ---------------- launch ----------------------------------------------------
extern "C" void kernel_launch(void* const* d_in, const int* in_sizes, int n_in,
                              void* d_out, int out_size)
{
    const float* hs = (const float*)d_in[0];
    const float* pe = (const float*)d_in[1];
    const float* Wq = (const float*)d_in[2];
    const float* Wk = (const float*)d_in[3];
    const float* Wv = (const float*)d_in[4];
    const float* Wo = (const float*)d_in[5];
    const float* Wp = (const float*)d_in[6];
    const float* bu = (const float*)d_in[7];
    const float* bv = (const float*)d_in[8];
    float* out = (float*)d_out;

    static int attr_done = 0;
    if (!attr_done) {
        cudaFuncSetAttribute(k_proj, cudaFuncAttributeMaxDynamicSharedMemorySize, DYN);
        cudaFuncSetAttribute(k_ac,   cudaFuncAttributeMaxDynamicSharedMemorySize, DYN4);
        cudaFuncSetAttribute(k_bd,   cudaFuncAttributeMaxDynamicSharedMemorySize, DYN4);
        cudaFuncSetAttribute(k_av,   cudaFuncAttributeMaxDynamicSharedMemorySize, DYNW);
        cudaFuncSetAttribute(k_out,  cudaFuncAttributeMaxDynamicSharedMemorySize, DYNW);
        attr_done = 1;
    }

    const int total = MHS*DD + PE_N + 5*DD*DD;
    k_split_all<<<(total + 255)/256, 256>>>(hs, pe, Wq, Wk, Wv, Wo, Wp);

    k_proj<<<dim3(16, 32, 4), 256, DYN>>>(bu, bv);
    k_ac <<<dim3(16, 8, BATCH*HH), 256, DYN4>>>();
    k_bd <<<dim3(18, 8, BATCH*HH), 256, DYN4>>>();
    k_softmax<<<BATCH*HH*TT/8, 256>>>();
    k_av <<<dim3(8, BATCH*HH), 256, DYNW>>>();
    k_out<<<dim3(8, 32), 256, DYNW>>>(out);
}